// round 17
// baseline (speedup 1.0000x reference)
#include <cuda_runtime.h>
#include <cuda_bf16.h>
#include <cstdint>

// Inputs (metadata order):
//   d_in[0] features  float32 [E*5]
//   d_in[1] values    float32 [E]
//   d_in[2] a0_weight float32 [5]
//   d_in[3] rows      int32   [E]
//   d_in[4] num_nodes int32   [1]
// Output: float32 [num_nodes]

// Primary kernel: zero the poisoned output. One float4 per thread, then
// signal programmatic completion so the PDL secondary's gridsync can
// release on WRITE completion instead of grid teardown.
__global__ void zero_all_kernel(float* __restrict__ out, int n) {
    int n4 = n >> 2;
    float4* out4 = (float4*)out;
    int i = blockIdx.x * blockDim.x + threadIdx.x;
    if (i < n4)
        out4[i] = make_float4(0.f, 0.f, 0.f, 0.f);
    int t = n4 * 4 + i;
    if (t < n) out[t] = 0.f;
#if __CUDA_ARCH__ >= 900
    cudaTriggerProgrammaticLaunchCompletion();
#endif
}

// Secondary kernel (PDL): front end (loads + math) runs CONCURRENTLY with the
// zeroing kernel; cudaGridDependencySynchronize() gates only the atomics.
// Structure identical to the proven 122us vec4 one-shot kernel.
__global__ __launch_bounds__(128) void scatter_dot_vec4_pdl_kernel(
    const float4* __restrict__ feat4,  // [E*5/4]
    const float4* __restrict__ vals4,  // [E/4]
    const float*  __restrict__ w,      // [5]
    const int4*   __restrict__ rows4,  // [E/4]
    float* __restrict__ out,
    int nQuads)                        // E/4
{
    const float w0 = __ldg(w + 0);
    const float w1 = __ldg(w + 1);
    const float w2 = __ldg(w + 2);
    const float w3 = __ldg(w + 3);
    const float w4 = __ldg(w + 4);

    int q = blockIdx.x * blockDim.x + threadIdx.x;
    if (q >= nQuads) return;

    const float4 f0 = __ldcs(feat4 + (size_t)q * 5 + 0);
    const float4 f1 = __ldcs(feat4 + (size_t)q * 5 + 1);
    const float4 f2 = __ldcs(feat4 + (size_t)q * 5 + 2);
    const float4 f3 = __ldcs(feat4 + (size_t)q * 5 + 3);
    const float4 f4 = __ldcs(feat4 + (size_t)q * 5 + 4);
    const float4 v  = __ldcs(vals4 + q);
    const int4   r  = __ldcs(rows4 + q);

    // edge0: f0.x f0.y f0.z f0.w f1.x
    float d0 = w0*f0.x + w1*f0.y + w2*f0.z + w3*f0.w + w4*f1.x;
    // edge1: f1.y f1.z f1.w f2.x f2.y
    float d1 = w0*f1.y + w1*f1.z + w2*f1.w + w3*f2.x + w4*f2.y;
    // edge2: f2.z f2.w f3.x f3.y f3.z
    float d2 = w0*f2.z + w1*f2.w + w2*f3.x + w3*f3.y + w4*f3.z;
    // edge3: f3.w f4.x f4.y f4.z f4.w
    float d3 = w0*f3.w + w1*f4.x + w2*f4.y + w3*f4.z + w4*f4.w;

    // Wait for the zeroing grid's writes (released at trigger, not teardown).
#if __CUDA_ARCH__ >= 900
    cudaGridDependencySynchronize();
#endif

    atomicAdd(out + r.x, v.x * d0);
    atomicAdd(out + r.y, v.y * d1);
    atomicAdd(out + r.z, v.z * d2);
    atomicAdd(out + r.w, v.w * d3);
}

// Scalar tail for E % 4 != 0 (not hit for E = 2^24, kept for generality).
__global__ void scatter_dot_tail_kernel(
    const float* __restrict__ feat,
    const float* __restrict__ vals,
    const float* __restrict__ w,
    const int*   __restrict__ rows,
    float* __restrict__ out,
    int start, int E)
{
    int e = start + blockIdx.x * blockDim.x + threadIdx.x;
    if (e >= E) return;
    const float* f = feat + (size_t)e * 5;
    float d = vals[e] * (w[0]*f[0] + w[1]*f[1] + w[2]*f[2] + w[3]*f[3] + w[4]*f[4]);
    atomicAdd(out + rows[e], d);
}

extern "C" void kernel_launch(void* const* d_in, const int* in_sizes, int n_in,
                              void* d_out, int out_size)
{
    const float* feat = (const float*)d_in[0];
    const float* vals = (const float*)d_in[1];
    const float* w    = (const float*)d_in[2];
    const int*   rows = (const int*)d_in[3];
    float* out = (float*)d_out;

    const int E = in_sizes[1];          // values has E elements
    const int N = out_size;             // num_nodes

    // Primary: zero the (poisoned) output; one element per thread so each
    // block triggers completion as early as possible.
    {
        int zb = 256;
        int n4 = N >> 2;
        int zg = (n4 + zb - 1) / zb;
        if (zg < 1) zg = 1;
        zero_all_kernel<<<zg, zb>>>(out, N);
    }

    const int nQuads = E / 4;
    if (nQuads > 0) {
        const int threads = 128;
        const int blocks = (nQuads + threads - 1) / threads;

        // Secondary with programmatic dependent launch: overlap its load
        // front-end with the zeroing kernel; atomics gated in-kernel.
        cudaLaunchConfig_t cfg = {};
        cfg.gridDim  = dim3(blocks, 1, 1);
        cfg.blockDim = dim3(threads, 1, 1);
        cfg.dynamicSmemBytes = 0;
        cfg.stream = 0;
        cudaLaunchAttribute attrs[1];
        attrs[0].id = cudaLaunchAttributeProgrammaticStreamSerialization;
        attrs[0].val.programmaticStreamSerializationAllowed = 1;
        cfg.attrs = attrs;
        cfg.numAttrs = 1;

        cudaLaunchKernelEx(&cfg, scatter_dot_vec4_pdl_kernel,
                           (const float4*)feat, (const float4*)vals, w,
                           (const int4*)rows, out, nQuads);
    }
    const int tailStart = nQuads * 4;
    if (E - tailStart > 0) {
        int n = E - tailStart;
        scatter_dot_tail_kernel<<<(n + 255) / 256, 256>>>(
            feat, vals, w, rows, out, tailStart, E);
    }
}